// round 5
// baseline (speedup 1.0000x reference)
#include <cuda_runtime.h>
#include <cuda_bf16.h>
#include <math.h>
#include <cstdint>

// Problem dims
#define TT   512
#define BB   64
#define EE   300
#define HH   512
#define LL   5
#define TH3  1536   // 3*H

// ---------------- scratch (device globals; no allocation allowed) -------------
__device__ float g_xp [(size_t)TT * TH3 * BB];   // input projections, layout [T][3H][B]
__device__ float g_ys0[(size_t)TT * HH  * BB];   // layer0 hidden seq, layout [T][H][B]
__device__ float g_ys1[(size_t)TT * HH  * BB];   // layer1 hidden seq, layout [T][H][B]

__device__ unsigned g_bar_count = 0;
__device__ unsigned g_bar_sense = 0;

// Sense-reversing grid barrier. All CTAs must be co-resident (128 CTAs on 148
// SMs, 1 CTA/SM fits). State returns to {0,0} after an even number of uses per
// launch (we use 512 per recurrence launch).
__device__ __forceinline__ void grid_barrier(unsigned* lsense, int nb) {
    __syncthreads();
    if (threadIdx.x == 0) {
        unsigned s = *lsense ^ 1u;
        __threadfence();                       // release h writes (cumulative)
        if (atomicAdd(&g_bar_count, 1u) == (unsigned)(nb - 1)) {
            g_bar_count = 0u;                  // all arrived; safe to reset
            __threadfence();
            atomicExch(&g_bar_sense, s);       // release
        } else {
            volatile unsigned* vs = &g_bar_sense;
            while (*vs != s) { __nanosleep(64); }
        }
        __threadfence();                       // acquire (cumulative)
    }
    __syncthreads();
    *lsense ^= 1u;
}

// ================= GEMM 1: embedding gather + input projection ================
// C[m][n] = sum_k emb[texts[m]][k] * W[n][k] + bias[n], K=300, m = t*64+b.
// Written transposed: g_xp[(t*1536+n)*64 + b].
__global__ __launch_bounds__(256) void k_gemm_embed(
    const int*   __restrict__ texts,
    const float* __restrict__ emb,
    const float* __restrict__ W,
    const float* __restrict__ bias)
{
    __shared__ __align__(16) float As[16][132];
    __shared__ __align__(16) float Bs[16][132];
    const int K = EE;

    int tid = threadIdx.x;
    int bn = blockIdx.x, bm = blockIdx.y;
    int tm = tid & 15;        // fast in m (for coalesced epilogue)
    int tn = tid >> 4;        // 16 n-groups

    float acc[8][8];
#pragma unroll
    for (int i = 0; i < 8; i++)
#pragma unroll
        for (int j = 0; j < 8; j++) acc[i][j] = 0.f;

    const int nkt = (K + 15) / 16;   // 19 (304, zero-padded tail)
    for (int kt = 0; kt < nkt; kt++) {
        int k0 = kt * 16;
        // A tile: gather rows of emb (transpose-store into As[k][m])
#pragma unroll
        for (int i = 0; i < 2; i++) {
            int idx = tid + i * 256;          // 512 float4 loads
            int m = idx >> 2, kq = idx & 3;
            int kg = k0 + kq * 4;
            float4 v = make_float4(0.f, 0.f, 0.f, 0.f);
            if (kg < K) {
                int row = texts[bm * 128 + m];
                v = *(const float4*)(emb + (size_t)row * K + kg);
            }
            As[kq * 4 + 0][m] = v.x; As[kq * 4 + 1][m] = v.y;
            As[kq * 4 + 2][m] = v.z; As[kq * 4 + 3][m] = v.w;
        }
        // B tile: Wih rows
#pragma unroll
        for (int i = 0; i < 2; i++) {
            int idx = tid + i * 256;
            int n = idx >> 2, kq = idx & 3;
            int kg = k0 + kq * 4;
            float4 v = make_float4(0.f, 0.f, 0.f, 0.f);
            if (kg < K) v = *(const float4*)(W + (size_t)(bn * 128 + n) * K + kg);
            Bs[kq * 4 + 0][n] = v.x; Bs[kq * 4 + 1][n] = v.y;
            Bs[kq * 4 + 2][n] = v.z; Bs[kq * 4 + 3][n] = v.w;
        }
        __syncthreads();
#pragma unroll
        for (int kk = 0; kk < 16; kk++) {
            float a[8];
#pragma unroll
            for (int i = 0; i < 8; i++) a[i] = As[kk][tm + i * 16];
            float4 b0 = *(const float4*)&Bs[kk][tn * 8];
            float4 b1 = *(const float4*)&Bs[kk][tn * 8 + 4];
            float bv[8] = {b0.x, b0.y, b0.z, b0.w, b1.x, b1.y, b1.z, b1.w};
#pragma unroll
            for (int i = 0; i < 8; i++)
#pragma unroll
                for (int j = 0; j < 8; j++)
                    acc[i][j] = fmaf(a[i], bv[j], acc[i][j]);
        }
        __syncthreads();
    }
    float bv[8];
#pragma unroll
    for (int j = 0; j < 8; j++) bv[j] = bias[bn * 128 + tn * 8 + j];
#pragma unroll
    for (int i = 0; i < 8; i++) {
        int m = bm * 128 + tm + i * 16;
        int t = m >> 6, b = m & 63;
        float* op = g_xp + (size_t)t * TH3 * BB + b;
#pragma unroll
        for (int j = 0; j < 8; j++) {
            int n = bn * 128 + tn * 8 + j;
            op[(size_t)n * BB] = acc[i][j] + bv[j];
        }
    }
}

// ========== GEMM 2: layer-1 input projection from transposed hidden seq =======
// A[m][k] = g_ys0[(t*H + k)*B + b], K=512; same epilogue layout into g_xp.
__global__ __launch_bounds__(256) void k_gemm_h(
    const float* __restrict__ W,
    const float* __restrict__ bias)
{
    __shared__ __align__(16) float As[16][132];
    __shared__ __align__(16) float Bs[16][132];
    const int K = HH;
    const float* __restrict__ A = g_ys0;

    int tid = threadIdx.x;
    int bn = blockIdx.x, bm = blockIdx.y;
    int tm = tid & 15;
    int tn = tid >> 4;

    float acc[8][8];
#pragma unroll
    for (int i = 0; i < 8; i++)
#pragma unroll
        for (int j = 0; j < 8; j++) acc[i][j] = 0.f;

    for (int kt = 0; kt < K / 16; kt++) {
        int k0 = kt * 16;
        // A tile: m-contiguous float4 loads from [T][H][B] layout
#pragma unroll
        for (int i = 0; i < 2; i++) {
            int idx = tid + i * 256;
            int k = idx >> 5, m4 = idx & 31;
            int mg = bm * 128 + m4 * 4;
            int t = mg >> 6, b = mg & 63;
            float4 v = *(const float4*)(A + ((size_t)t * HH + (k0 + k)) * BB + b);
            *(float4*)&As[k][m4 * 4] = v;
        }
#pragma unroll
        for (int i = 0; i < 2; i++) {
            int idx = tid + i * 256;
            int n = idx >> 2, kq = idx & 3;
            float4 v = *(const float4*)(W + (size_t)(bn * 128 + n) * K + k0 + kq * 4);
            Bs[kq * 4 + 0][n] = v.x; Bs[kq * 4 + 1][n] = v.y;
            Bs[kq * 4 + 2][n] = v.z; Bs[kq * 4 + 3][n] = v.w;
        }
        __syncthreads();
#pragma unroll
        for (int kk = 0; kk < 16; kk++) {
            float a[8];
#pragma unroll
            for (int i = 0; i < 8; i++) a[i] = As[kk][tm + i * 16];
            float4 b0 = *(const float4*)&Bs[kk][tn * 8];
            float4 b1 = *(const float4*)&Bs[kk][tn * 8 + 4];
            float bv[8] = {b0.x, b0.y, b0.z, b0.w, b1.x, b1.y, b1.z, b1.w};
#pragma unroll
            for (int i = 0; i < 8; i++)
#pragma unroll
                for (int j = 0; j < 8; j++)
                    acc[i][j] = fmaf(a[i], bv[j], acc[i][j]);
        }
        __syncthreads();
    }
    float bv[8];
#pragma unroll
    for (int j = 0; j < 8; j++) bv[j] = bias[bn * 128 + tn * 8 + j];
#pragma unroll
    for (int i = 0; i < 8; i++) {
        int m = bm * 128 + tm + i * 16;
        int t = m >> 6, b = m & 63;
        float* op = g_xp + (size_t)t * TH3 * BB + b;
#pragma unroll
        for (int j = 0; j < 8; j++) {
            int n = bn * 128 + tn * 8 + j;
            op[(size_t)n * BB] = acc[i][j] + bv[j];
        }
    }
}

// ==================== persistent GRU recurrence (one layer) ===================
// Grid 128 CTAs x 512 thr. CTA owns 4 hidden cols j (12 Whh rows in SMEM).
// Warp w: jl=w&3 (which j), ksec=w>>2 (K/4 slice). Lane covers b={2l,2l+1}.
__device__ __forceinline__ float sigm(float x) { return 1.f / (1.f + expf(-x)); }

__global__ __launch_bounds__(512, 1) void k_recur(
    const float* __restrict__ Whh,   // [3H][H]
    const float* __restrict__ bhh,   // [3H]
    int layer)
{
    __shared__ __align__(16) float Ws[12 * 512];
    __shared__ __align__(16) float red[4 * 4 * 3 * 64];   // [ksec][jl][gate][b]
    __shared__ float bhh_s[12];

    float* __restrict__ ys = layer ? g_ys1 : g_ys0;
    const float* __restrict__ xp = g_xp;

    const int tid   = threadIdx.x;
    const int jbase = blockIdx.x * 4;
    const int nb    = gridDim.x;

    // load Whh slice: local row lr = g*4+jl  ->  global row g*H + (jbase+jl)
    for (int idx = tid; idx < 12 * 512; idx += 512) {
        int lr = idx >> 9, k = idx & 511;
        int g = lr >> 2, jl = lr & 3;
        Ws[idx] = Whh[((size_t)(g * HH + jbase + jl)) * HH + k];
    }
    if (tid < 12) {
        int g = tid >> 2, jl = tid & 3;
        bhh_s[tid] = bhh[g * HH + jbase + jl];
    }
    __syncthreads();

    const int warp = tid >> 5;
    const int lane = tid & 31;
    const int jl   = warp & 3;
    const int ksec = warp >> 2;
    const int kbase = ksec * 128;

    const float* w0 = Ws + (0 * 4 + jl) * 512 + kbase;
    const float* w1 = Ws + (1 * 4 + jl) * 512 + kbase;
    const float* w2 = Ws + (2 * 4 + jl) * 512 + kbase;

    unsigned lsense = 0;

    for (int t = 0; t < TT; t++) {
        if (t > 0) {
            const float* hb = ys + ((size_t)(t - 1) * HH + kbase) * BB + 2 * lane;
            float a00 = 0.f, a01 = 0.f, a10 = 0.f, a11 = 0.f, a20 = 0.f, a21 = 0.f;
#pragma unroll 2
            for (int k4 = 0; k4 < 32; k4++) {
                const float* hk = hb + k4 * 4 * BB;
                float2 h0 = __ldcg((const float2*)(hk));
                float2 h1 = __ldcg((const float2*)(hk + BB));
                float2 h2 = __ldcg((const float2*)(hk + 2 * BB));
                float2 h3 = __ldcg((const float2*)(hk + 3 * BB));
                float4 wa = *(const float4*)(w0 + k4 * 4);
                float4 wb = *(const float4*)(w1 + k4 * 4);
                float4 wc = *(const float4*)(w2 + k4 * 4);
                a00 = fmaf(wa.x, h0.x, fmaf(wa.y, h1.x, fmaf(wa.z, h2.x, fmaf(wa.w, h3.x, a00))));
                a01 = fmaf(wa.x, h0.y, fmaf(wa.y, h1.y, fmaf(wa.z, h2.y, fmaf(wa.w, h3.y, a01))));
                a10 = fmaf(wb.x, h0.x, fmaf(wb.y, h1.x, fmaf(wb.z, h2.x, fmaf(wb.w, h3.x, a10))));
                a11 = fmaf(wb.x, h0.y, fmaf(wb.y, h1.y, fmaf(wb.z, h2.y, fmaf(wb.w, h3.y, a11))));
                a20 = fmaf(wc.x, h0.x, fmaf(wc.y, h1.x, fmaf(wc.z, h2.x, fmaf(wc.w, h3.x, a20))));
                a21 = fmaf(wc.x, h0.y, fmaf(wc.y, h1.y, fmaf(wc.z, h2.y, fmaf(wc.w, h3.y, a21))));
            }
            int rb = ((ksec * 4 + jl) * 3 + 0) * 64 + 2 * lane;
            red[rb]            = a00; red[rb + 1]            = a01;
            red[rb + 64]       = a10; red[rb + 65]           = a11;
            red[rb + 128]      = a20; red[rb + 129]          = a21;
        }
        __syncthreads();

        if (tid < 256) {
            int rjl = tid >> 6, b = tid & 63;
            int j = jbase + rjl;
            float s0 = bhh_s[0 + rjl];
            float s1 = bhh_s[4 + rjl];
            float s2 = bhh_s[8 + rjl];
            if (t > 0) {
#pragma unroll
                for (int ks = 0; ks < 4; ks++) {
                    int base = ((ks * 4 + rjl) * 3) * 64 + b;
                    s0 += red[base];
                    s1 += red[base + 64];
                    s2 += red[base + 128];
                }
            }
            const float* xpb = xp + (size_t)t * TH3 * BB + b;
            float xr = xpb[(size_t)(0 * HH + j) * BB];
            float xz = xpb[(size_t)(1 * HH + j) * BB];
            float xn = xpb[(size_t)(2 * HH + j) * BB];
            float r = sigm(xr + s0);
            float z = sigm(xz + s1);
            float n = tanhf(xn + r * s2);
            float hprev = (t > 0) ? __ldcg(ys + ((size_t)(t - 1) * HH + j) * BB + b) : 0.f;
            ys[((size_t)t * HH + j) * BB + b] = (1.f - z) * n + z * hprev;
        }
        grid_barrier(&lsense, nb);
    }
}

// ==================== mean over batch + FC head ===============================
// pooled[t][h] = mean_b ys1[t][h][b]; out[t][l] = pooled . fc_W[l] + fc_b[l]
__global__ __launch_bounds__(256) void k_pool(
    const float* __restrict__ fcW,
    const float* __restrict__ fcb,
    float*       __restrict__ out)
{
    int t = blockIdx.x;
    const float* base = g_ys1 + (size_t)t * HH * BB;
    int w = threadIdx.x >> 5, l = threadIdx.x & 31;

    float acc[LL];
#pragma unroll
    for (int j = 0; j < LL; j++) acc[j] = 0.f;

    for (int h = w; h < HH; h += 8) {
        float s = base[h * BB + l] + base[h * BB + 32 + l];
#pragma unroll
        for (int off = 16; off >= 1; off >>= 1)
            s += __shfl_xor_sync(0xffffffffu, s, off);
        if (l == 0) {
            float p = s * (1.f / 64.f);
#pragma unroll
            for (int j = 0; j < LL; j++) acc[j] = fmaf(p, fcW[j * HH + h], acc[j]);
        }
    }
    __shared__ float sred[8][LL];
    if (l == 0) {
#pragma unroll
        for (int j = 0; j < LL; j++) sred[w][j] = acc[j];
    }
    __syncthreads();
    if (threadIdx.x < LL) {
        float s = fcb[threadIdx.x];
#pragma unroll
        for (int ww = 0; ww < 8; ww++) s += sred[ww][threadIdx.x];
        out[t * LL + threadIdx.x] = s;
    }
}

// ============================== launch ========================================
extern "C" void kernel_launch(void* const* d_in, const int* in_sizes, int n_in,
                              void* d_out, int out_size) {
    const int*   texts = (const int*)  d_in[0];
    const float* emb   = (const float*)d_in[1];
    const float* Wih0  = (const float*)d_in[2];
    const float* Whh0  = (const float*)d_in[3];
    const float* bih0  = (const float*)d_in[4];
    const float* bhh0  = (const float*)d_in[5];
    const float* Wih1  = (const float*)d_in[6];
    const float* Whh1  = (const float*)d_in[7];
    const float* bih1  = (const float*)d_in[8];
    const float* bhh1  = (const float*)d_in[9];
    const float* fcW   = (const float*)d_in[10];
    const float* fcb   = (const float*)d_in[11];
    float* out = (float*)d_out;

    dim3 gemm_grid(TH3 / 128, (TT * BB) / 128);   // (12, 256)

    // Layer 0
    k_gemm_embed<<<gemm_grid, 256>>>(texts, emb, Wih0, bih0);
    k_recur<<<128, 512>>>(Whh0, bhh0, 0);
    // Layer 1
    k_gemm_h<<<gemm_grid, 256>>>(Wih1, bih1);
    k_recur<<<128, 512>>>(Whh1, bhh1, 1);
    // Head
    k_pool<<<TT, 256>>>(fcW, fcb, out);
}

// round 8
// speedup vs baseline: 1.1631x; 1.1631x over previous
#include <cuda_runtime.h>
#include <cuda_bf16.h>
#include <math.h>
#include <cstdint>

// Problem dims
#define TT   512
#define BB   64
#define EE   300
#define HH   512
#define LL   5
#define TH3  1536   // 3*H

#define KP0  320    // padded K for layer-0 input GEMM (E=300 -> 320, 10 stages of 32)
#define KP1  512    // K for layer-1 input GEMM (16 stages of 32)

// ---------------- scratch (device globals; no allocation allowed) -------------
__device__ float g_xp [(size_t)TT * TH3 * BB];   // input projections [T][3H][B]
__device__ float g_ys0[(size_t)TT * HH  * BB];   // layer0 hidden seq [T][H][B]
__device__ float g_ys1[(size_t)TT * HH  * BB];   // layer1 hidden seq [T][H][B]

// split-bf16 (hi+lo) operands for tensor-core GEMMs
__device__ __nv_bfloat16 g_embh[(size_t)30000 * KP0];
__device__ __nv_bfloat16 g_embl[(size_t)30000 * KP0];
__device__ __nv_bfloat16 g_w0h [(size_t)TH3 * KP0];
__device__ __nv_bfloat16 g_w0l [(size_t)TH3 * KP0];
__device__ __nv_bfloat16 g_w1h [(size_t)TH3 * KP1];
__device__ __nv_bfloat16 g_w1l [(size_t)TH3 * KP1];
__device__ __nv_bfloat16 g_a1h [(size_t)TT * BB * KP1];   // ys0 transposed [m=t*64+b][k]
__device__ __nv_bfloat16 g_a1l [(size_t)TT * BB * KP1];

__device__ unsigned g_bar_count = 0;
__device__ unsigned g_bar_sense = 0;

// ======================= helpers (base ISA only; no sm_103a-only ops) =========
__device__ __forceinline__ uint32_t smem_u32(const void* p) {
    uint32_t a;
    asm("{ .reg .u64 t; cvta.to.shared.u64 t, %1; cvt.u32.u64 %0, t; }" : "=r"(a) : "l"(p));
    return a;
}
__device__ __forceinline__ void cp16(uint32_t dst, const void* src) {
    asm volatile("cp.async.cg.shared.global [%0], [%1], 16;" :: "r"(dst), "l"(src));
}
__device__ __forceinline__ void cp_commit() { asm volatile("cp.async.commit_group;" ::: "memory"); }
__device__ __forceinline__ void cp_wait1()  { asm volatile("cp.async.wait_group 1;" ::: "memory"); }
__device__ __forceinline__ void cp_wait0()  { asm volatile("cp.async.wait_group 0;" ::: "memory"); }

__device__ __forceinline__ void mma_bf16(float* c, uint32_t a0, uint32_t a1,
                                         uint32_t a2, uint32_t a3,
                                         uint32_t b0, uint32_t b1) {
    asm volatile(
        "mma.sync.aligned.m16n8k16.row.col.f32.bf16.bf16.f32 "
        "{%0,%1,%2,%3}, {%4,%5,%6,%7}, {%8,%9}, {%0,%1,%2,%3};"
        : "+f"(c[0]), "+f"(c[1]), "+f"(c[2]), "+f"(c[3])
        : "r"(a0), "r"(a1), "r"(a2), "r"(a3), "r"(b0), "r"(b1));
}

// Sense-reversing grid barrier. All CTAs co-resident (128 on 148 SMs). State
// returns to {0,0} after an even number of uses per launch (512 per launch).
__device__ __forceinline__ void grid_barrier(unsigned* lsense, int nb) {
    __syncthreads();
    if (threadIdx.x == 0) {
        unsigned s = *lsense ^ 1u;
        __threadfence();
        if (atomicAdd(&g_bar_count, 1u) == (unsigned)(nb - 1)) {
            g_bar_count = 0u;
            __threadfence();
            atomicExch(&g_bar_sense, s);
        } else {
            volatile unsigned* vs = &g_bar_sense;
            while (*vs != s) { __nanosleep(32); }
        }
        __threadfence();
    }
    __syncthreads();
    *lsense ^= 1u;
}

// =================== conversion kernels (fp32 -> bf16 hi/lo) ==================
__global__ __launch_bounds__(256) void k_conv_pair(
    const float* __restrict__ src, __nv_bfloat16* __restrict__ dh,
    __nv_bfloat16* __restrict__ dl, int N, int Ks, int Kp)
{
    size_t total = (size_t)N * Kp;
    for (size_t idx = (size_t)blockIdx.x * blockDim.x + threadIdx.x; idx < total;
         idx += (size_t)gridDim.x * blockDim.x) {
        int n = (int)(idx / Kp), k = (int)(idx - (size_t)n * Kp);
        float v = (k < Ks) ? src[(size_t)n * Ks + k] : 0.f;
        __nv_bfloat16 hi = __float2bfloat16(v);
        dh[idx] = hi;
        dl[idx] = __float2bfloat16(v - __bfloat162float(hi));
    }
}

// transpose-convert g_ys0 [T][H][B] -> g_a1h/l [m=t*64+b][k=H]
__global__ __launch_bounds__(256) void k_conv_ys0() {
    __shared__ float smt[64][65];
    int t = blockIdx.x, kb = blockIdx.y;     // grid (512, 8)
    const float* src = g_ys0 + ((size_t)t * HH + kb * 64) * BB;
    for (int i = threadIdx.x; i < 4096; i += 256) {
        int k = i >> 6, b = i & 63;
        smt[k][b] = src[(size_t)k * BB + b];
    }
    __syncthreads();
    for (int i = threadIdx.x; i < 4096; i += 256) {
        int b = i >> 6, k = i & 63;
        float v = smt[k][b];
        __nv_bfloat16 hi = __float2bfloat16(v);
        size_t o = ((size_t)t * 64 + b) * KP1 + kb * 64 + k;
        g_a1h[o] = hi;
        g_a1l[o] = __float2bfloat16(v - __bfloat162float(hi));
    }
}

// ============== HMMA split-bf16 GEMM (input projections) ======================
// C[m][n] = sum_k (Ah+Al)[row(m)][k]*(Bh+Bl)[n][k] + bias[n]  (drops Al*Bl).
// CTA 256 thr, tile 128x128, K stage 32, cp.async double buffer.
// SMEM tile: 128 rows x 32 bf16, row stride 40 bf16 (80B) -> conflict-free LDS.
#define STRD32 20                       // row stride in b32 units
#define TILE_BYTES (128 * 80)           // 10240
#define STAGE_BYTES (4 * TILE_BYTES)    // Ah, Al, Bh, Bl
#define GEMM_SMEM (2 * STAGE_BYTES)     // 81920

__global__ __launch_bounds__(256) void k_mma_gemm(
    const __nv_bfloat16* __restrict__ Ah, const __nv_bfloat16* __restrict__ Al,
    const int* __restrict__ rowidx,     // null => identity (row = m)
    int Kpad, int S,
    const __nv_bfloat16* __restrict__ Bh, const __nv_bfloat16* __restrict__ Bl,
    const float* __restrict__ bias)
{
    extern __shared__ __align__(128) char smem[];
    __shared__ int   rows_s[128];
    __shared__ float bias_s[128];

    const int tid = threadIdx.x;
    const int bn = blockIdx.x, bm = blockIdx.y;
    const uint32_t sb = smem_u32(smem);

    if (tid < 128) {
        int m = bm * 128 + tid;
        rows_s[tid] = rowidx ? rowidx[m] : m;
        bias_s[tid] = bias[bn * 128 + tid];
    }
    __syncthreads();

    auto load_stage = [&](int s) {
        uint32_t buf = sb + (uint32_t)(s & 1) * STAGE_BYTES;
        int k0 = s * 32;
#pragma unroll
        for (int i = 0; i < 8; i++) {
            int idx = tid + i * 256;          // 2048 cp16 total
            int tile = idx >> 9;
            int loc = idx & 511;
            int r = loc >> 2, c = loc & 3;
            const __nv_bfloat16* src;
            if (tile < 2) {
                src = (tile == 0 ? Ah : Al) + (size_t)rows_s[r] * Kpad + k0 + c * 8;
            } else {
                src = (tile == 2 ? Bh : Bl) + (size_t)(bn * 128 + r) * Kpad + k0 + c * 8;
            }
            cp16(buf + tile * TILE_BYTES + r * 80 + c * 16, src);
        }
        cp_commit();
    };

    load_stage(0);
    if (S > 1) load_stage(1);

    const int wid = tid >> 5, lane = tid & 31;
    const int wm = wid & 3, wn = wid >> 2;
    const int g = lane >> 2, q = lane & 3;

    float acc[2][8][4];
#pragma unroll
    for (int mt = 0; mt < 2; mt++)
#pragma unroll
        for (int nt = 0; nt < 8; nt++)
#pragma unroll
            for (int e = 0; e < 4; e++) acc[mt][nt][e] = 0.f;

    for (int s = 0; s < S; s++) {
        if (s + 1 < S) cp_wait1(); else cp_wait0();
        __syncthreads();
        const char* buf = smem + (size_t)(s & 1) * STAGE_BYTES;
        const uint32_t* Ah32 = (const uint32_t*)(buf);
        const uint32_t* Al32 = (const uint32_t*)(buf + TILE_BYTES);
        const uint32_t* Bh32 = (const uint32_t*)(buf + 2 * TILE_BYTES);
        const uint32_t* Bl32 = (const uint32_t*)(buf + 3 * TILE_BYTES);

#pragma unroll
        for (int kh = 0; kh < 2; kh++) {
            const int kb = kh * 8;            // b32 offset of k16 half
            uint32_t ah[2][4], al[2][4];
#pragma unroll
            for (int mt = 0; mt < 2; mt++) {
                int r0 = (wm * 32 + mt * 16 + g) * STRD32;
                int r1 = r0 + 8 * STRD32;
                ah[mt][0] = Ah32[r0 + kb + q];
                ah[mt][1] = Ah32[r1 + kb + q];
                ah[mt][2] = Ah32[r0 + kb + q + 4];
                ah[mt][3] = Ah32[r1 + kb + q + 4];
                al[mt][0] = Al32[r0 + kb + q];
                al[mt][1] = Al32[r1 + kb + q];
                al[mt][2] = Al32[r0 + kb + q + 4];
                al[mt][3] = Al32[r1 + kb + q + 4];
            }
#pragma unroll
            for (int nt = 0; nt < 8; nt++) {
                int nr = (wn * 64 + nt * 8 + g) * STRD32;
                uint32_t bh0 = Bh32[nr + kb + q];
                uint32_t bh1 = Bh32[nr + kb + q + 4];
                uint32_t bl0 = Bl32[nr + kb + q];
                uint32_t bl1 = Bl32[nr + kb + q + 4];
#pragma unroll
                for (int mt = 0; mt < 2; mt++) {
                    mma_bf16(acc[mt][nt], ah[mt][0], ah[mt][1], ah[mt][2], ah[mt][3], bh0, bh1);
                    mma_bf16(acc[mt][nt], ah[mt][0], ah[mt][1], ah[mt][2], ah[mt][3], bl0, bl1);
                    mma_bf16(acc[mt][nt], al[mt][0], al[mt][1], al[mt][2], al[mt][3], bh0, bh1);
                }
            }
        }
        __syncthreads();
        if (s + 2 < S) load_stage(s + 2);
    }

    // epilogue: C row r -> m = bm*128+r -> (t=m>>6, b=m&63); col c -> n.
    // g_xp[(t*TH3+n)*64 + b]  += bias[n]
#pragma unroll
    for (int mt = 0; mt < 2; mt++) {
        int r0 = wm * 32 + mt * 16 + g;
        int m0 = bm * 128 + r0;
        int m1 = m0 + 8;
        float* p0 = g_xp + ((size_t)(m0 >> 6) * TH3) * BB + (m0 & 63);
        float* p1 = g_xp + ((size_t)(m1 >> 6) * TH3) * BB + (m1 & 63);
#pragma unroll
        for (int nt = 0; nt < 8; nt++) {
            int c = wn * 64 + nt * 8 + q * 2;
            int n0 = bn * 128 + c;
            float bv0 = bias_s[c], bv1 = bias_s[c + 1];
            p0[(size_t)n0 * BB]       = acc[mt][nt][0] + bv0;
            p0[(size_t)(n0 + 1) * BB] = acc[mt][nt][1] + bv1;
            p1[(size_t)n0 * BB]       = acc[mt][nt][2] + bv0;
            p1[(size_t)(n0 + 1) * BB] = acc[mt][nt][3] + bv1;
        }
    }
}

// ==================== persistent GRU recurrence (one layer) ===================
// Grid 128 CTAs x 512 thr. CTA owns 4 hidden cols j (12 Whh rows in SMEM).
// Warp w: jl=w&3 (which j), ksec=w>>2 (K/4 slice). Lane covers b={2l,2l+1}.
__device__ __forceinline__ float fsigm(float x) {
    return __fdividef(1.f, 1.f + __expf(-x));
}
__device__ __forceinline__ float ftanh(float x) {
    return 1.f - __fdividef(2.f, 1.f + __expf(2.f * x));
}

__global__ __launch_bounds__(512, 1) void k_recur(
    const float* __restrict__ Whh,   // [3H][H]
    const float* __restrict__ bhh,   // [3H]
    int layer)
{
    __shared__ __align__(16) float Ws[12 * 512];
    __shared__ __align__(16) float red[4 * 4 * 3 * 64];   // [ksec][jl][gate][b]
    __shared__ float bhh_s[12];

    float* __restrict__ ys = layer ? g_ys1 : g_ys0;
    const float* __restrict__ xp = g_xp;

    const int tid   = threadIdx.x;
    const int jbase = blockIdx.x * 4;
    const int nb    = gridDim.x;

    for (int idx = tid; idx < 12 * 512; idx += 512) {
        int lr = idx >> 9, k = idx & 511;
        int g = lr >> 2, jl = lr & 3;
        Ws[idx] = Whh[((size_t)(g * HH + jbase + jl)) * HH + k];
    }
    if (tid < 12) {
        int g = tid >> 2, jl = tid & 3;
        bhh_s[tid] = bhh[g * HH + jbase + jl];
    }
    __syncthreads();

    const int warp = tid >> 5;
    const int lane = tid & 31;
    const int jl   = warp & 3;
    const int ksec = warp >> 2;
    const int kbase = ksec * 128;

    const float* w0 = Ws + (0 * 4 + jl) * 512 + kbase;
    const float* w1 = Ws + (1 * 4 + jl) * 512 + kbase;
    const float* w2 = Ws + (2 * 4 + jl) * 512 + kbase;

    // tail-thread persistent state
    const int rjl = tid >> 6, rb = tid & 63;       // valid for tid<256
    float hq = 0.f;                                 // h(t-1)[jbase+rjl][rb]

    unsigned lsense = 0;

    for (int t = 0; t < TT; t++) {
        // prefetch xp for this step (consumed after the matvec phase)
        float xr = 0.f, xz = 0.f, xn = 0.f;
        if (tid < 256) {
            const float* xpb = xp + (size_t)t * TH3 * BB + rb;
            int j = jbase + rjl;
            xr = __ldcg(xpb + (size_t)(0 * HH + j) * BB);
            xz = __ldcg(xpb + (size_t)(1 * HH + j) * BB);
            xn = __ldcg(xpb + (size_t)(2 * HH + j) * BB);
        }

        if (t > 0) {
            const float* hb = ys + ((size_t)(t - 1) * HH + kbase) * BB + 2 * lane;
            float a00 = 0.f, a01 = 0.f, a10 = 0.f, a11 = 0.f, a20 = 0.f, a21 = 0.f;
#pragma unroll 2
            for (int k4 = 0; k4 < 32; k4++) {
                const float* hk = hb + k4 * 4 * BB;
                float2 h0 = __ldcg((const float2*)(hk));
                float2 h1 = __ldcg((const float2*)(hk + BB));
                float2 h2 = __ldcg((const float2*)(hk + 2 * BB));
                float2 h3 = __ldcg((const float2*)(hk + 3 * BB));
                float4 wa = *(const float4*)(w0 + k4 * 4);
                float4 wb = *(const float4*)(w1 + k4 * 4);
                float4 wc = *(const float4*)(w2 + k4 * 4);
                a00 = fmaf(wa.x, h0.x, fmaf(wa.y, h1.x, fmaf(wa.z, h2.x, fmaf(wa.w, h3.x, a00))));
                a01 = fmaf(wa.x, h0.y, fmaf(wa.y, h1.y, fmaf(wa.z, h2.y, fmaf(wa.w, h3.y, a01))));
                a10 = fmaf(wb.x, h0.x, fmaf(wb.y, h1.x, fmaf(wb.z, h2.x, fmaf(wb.w, h3.x, a10))));
                a11 = fmaf(wb.x, h0.y, fmaf(wb.y, h1.y, fmaf(wb.z, h2.y, fmaf(wb.w, h3.y, a11))));
                a20 = fmaf(wc.x, h0.x, fmaf(wc.y, h1.x, fmaf(wc.z, h2.x, fmaf(wc.w, h3.x, a20))));
                a21 = fmaf(wc.x, h0.y, fmaf(wc.y, h1.y, fmaf(wc.z, h2.y, fmaf(wc.w, h3.y, a21))));
            }
            int rbi = ((ksec * 4 + jl) * 3 + 0) * 64 + 2 * lane;
            red[rbi]       = a00; red[rbi + 1]   = a01;
            red[rbi + 64]  = a10; red[rbi + 65]  = a11;
            red[rbi + 128] = a20; red[rbi + 129] = a21;
        }
        __syncthreads();

        if (tid < 256) {
            float s0 = bhh_s[0 + rjl];
            float s1 = bhh_s[4 + rjl];
            float s2 = bhh_s[8 + rjl];
            if (t > 0) {
#pragma unroll
                for (int ks = 0; ks < 4; ks++) {
                    int base = ((ks * 4 + rjl) * 3) * 64 + rb;
                    s0 += red[base];
                    s1 += red[base + 64];
                    s2 += red[base + 128];
                }
            }
            float r = fsigm(xr + s0);
            float z = fsigm(xz + s1);
            float n = ftanh(xn + r * s2);
            float hnew = (1.f - z) * n + z * hq;
            hq = hnew;
            ys[((size_t)t * HH + (jbase + rjl)) * BB + rb] = hnew;
        }
        grid_barrier(&lsense, nb);
    }
}

// ==================== mean over batch + FC head ===============================
__global__ __launch_bounds__(256) void k_pool(
    const float* __restrict__ fcW,
    const float* __restrict__ fcb,
    float*       __restrict__ out)
{
    int t = blockIdx.x;
    const float* base = g_ys1 + (size_t)t * HH * BB;
    int w = threadIdx.x >> 5, l = threadIdx.x & 31;

    float acc[LL];
#pragma unroll
    for (int j = 0; j < LL; j++) acc[j] = 0.f;

    for (int h = w; h < HH; h += 8) {
        float s = base[h * BB + l] + base[h * BB + 32 + l];
#pragma unroll
        for (int off = 16; off >= 1; off >>= 1)
            s += __shfl_xor_sync(0xffffffffu, s, off);
        if (l == 0) {
            float p = s * (1.f / 64.f);
#pragma unroll
            for (int j = 0; j < LL; j++) acc[j] = fmaf(p, fcW[j * HH + h], acc[j]);
        }
    }
    __shared__ float sred[8][LL];
    if (l == 0) {
#pragma unroll
        for (int j = 0; j < LL; j++) sred[w][j] = acc[j];
    }
    __syncthreads();
    if (threadIdx.x < LL) {
        float s = fcb[threadIdx.x];
#pragma unroll
        for (int ww = 0; ww < 8; ww++) s += sred[ww][threadIdx.x];
        out[t * LL + threadIdx.x] = s;
    }
}

// ============================== launch ========================================
extern "C" void kernel_launch(void* const* d_in, const int* in_sizes, int n_in,
                              void* d_out, int out_size) {
    const int*   texts = (const int*)  d_in[0];
    const float* emb   = (const float*)d_in[1];
    const float* Wih0  = (const float*)d_in[2];
    const float* Whh0  = (const float*)d_in[3];
    const float* bih0  = (const float*)d_in[4];
    const float* bhh0  = (const float*)d_in[5];
    const float* Wih1  = (const float*)d_in[6];
    const float* Whh1  = (const float*)d_in[7];
    const float* bih1  = (const float*)d_in[8];
    const float* bhh1  = (const float*)d_in[9];
    const float* fcW   = (const float*)d_in[10];
    const float* fcb   = (const float*)d_in[11];
    float* out = (float*)d_out;

    cudaFuncSetAttribute(k_mma_gemm, cudaFuncAttributeMaxDynamicSharedMemorySize,
                         GEMM_SMEM);

    // resolve device-global scratch addresses for kernel params
    __nv_bfloat16 *embh, *embl, *w0h, *w0l, *w1h, *w1l, *a1h, *a1l;
    cudaGetSymbolAddress((void**)&embh, g_embh);
    cudaGetSymbolAddress((void**)&embl, g_embl);
    cudaGetSymbolAddress((void**)&w0h,  g_w0h);
    cudaGetSymbolAddress((void**)&w0l,  g_w0l);
    cudaGetSymbolAddress((void**)&w1h,  g_w1h);
    cudaGetSymbolAddress((void**)&w1l,  g_w1l);
    cudaGetSymbolAddress((void**)&a1h,  g_a1h);
    cudaGetSymbolAddress((void**)&a1l,  g_a1l);

    dim3 gemm_grid(TH3 / 128, (TT * BB) / 128);   // (12, 256)

    // conversions (static operands)
    k_conv_pair<<<8192, 256>>>(emb,  embh, embl, 30000, EE, KP0);
    k_conv_pair<<<1024, 256>>>(Wih0, w0h,  w0l,  TH3,   EE, KP0);
    k_conv_pair<<<1024, 256>>>(Wih1, w1h,  w1l,  TH3,   HH, KP1);

    // Layer 0: xp = emb[texts] @ Wih0^T + bih0 (HMMA), then recurrence
    k_mma_gemm<<<gemm_grid, 256, GEMM_SMEM>>>(embh, embl, texts, KP0, KP0 / 32,
                                              w0h, w0l, bih0);
    k_recur<<<128, 512>>>(Whh0, bhh0, 0);

    // Layer 1: transpose-convert ys0, xp = ys0 @ Wih1^T + bih1, recurrence
    k_conv_ys0<<<dim3(TT, HH / 64), 256>>>();
    k_mma_gemm<<<gemm_grid, 256, GEMM_SMEM>>>(a1h, a1l, nullptr, KP1, KP1 / 32,
                                              w1h, w1l, bih1);
    k_recur<<<128, 512>>>(Whh1, bhh1, 1);

    // Head
    k_pool<<<TT, 256>>>(fcW, fcb, out);
}